// round 1
// baseline (speedup 1.0000x reference)
#include <cuda_runtime.h>

// Fixed problem shape (validated against in_sizes at launch):
// glb_pos [B,T,J,3], glb_rot [B,T,J,4], glb_vel [B,T-1,J,3], root_rotation [B,T,1,4]
// Output: pos_out [B,T,J,3] followed by rot_out [B,T,J,4], both float32.

#define MAX_B 64
#define MAX_T 1024

// Scratch: per-(b,t) trajectory (x, 0, z) — pre-masked. 64*1024*3 floats = 786 KB.
__device__ float3 g_traj[MAX_B * MAX_T];

struct Q { float w, x, y, z; };

__device__ __forceinline__ Q qmul(Q a, Q b) {
    Q r;
    r.w = a.w * b.w - a.x * b.x - a.y * b.y - a.z * b.z;
    r.x = a.w * b.x + a.x * b.w + a.y * b.z - a.z * b.y;
    r.y = a.w * b.y - a.x * b.z + a.y * b.w + a.z * b.x;
    r.z = a.w * b.z + a.x * b.y - a.y * b.x + a.z * b.w;
    return r;
}

__device__ __forceinline__ float3 qapply(Q q, float3 p) {
    Q pq; pq.w = 0.f; pq.x = p.x; pq.y = p.y; pq.z = p.z;
    Q t = qmul(q, pq);
    Q c; c.w = q.w; c.x = -q.x; c.y = -q.y; c.z = -q.z;
    Q r = qmul(t, c);
    return make_float3(r.x, r.y, r.z);
}

__device__ __forceinline__ Q load_inv(const float4* __restrict__ root, int idx) {
    float4 v = __ldg(root + idx);      // (w, x, y, z) real-first
    Q q; q.w = v.x; q.x = -v.y; q.y = -v.z; q.z = -v.w;  // conjugate
    return q;
}

// ---------------------------------------------------------------------------
// Kernel 1: per-batch trajectory. Block b handles batch b; thread t handles
// time t. Exclusive scan of rotated joint-0 velocities + rotated joint-0
// position at t=0. Stores (x, 0, z) so the consumer just adds.
// ---------------------------------------------------------------------------
__global__ void __launch_bounds__(1024) traj_kernel(
    const float* __restrict__ glb_pos,
    const float* __restrict__ glb_vel,
    const float4* __restrict__ root,
    int T, int J)
{
    const int b = blockIdx.x;
    const int t = threadIdx.x;              // 0..1023 (== T)
    const int lane = t & 31, warp = t >> 5;

    __shared__ float3 s_wsum[32];
    __shared__ float3 s_pos0;

    Q inv = load_inv(root, b * T + t);

    // rotated velocity at joint 0, time t (valid for t < T-1)
    float3 v = make_float3(0.f, 0.f, 0.f);
    if (t < T - 1) {
        long base = ((long)(b * (T - 1) + t) * J) * 3;   // joint 0
        float3 p = make_float3(__ldg(glb_vel + base),
                               __ldg(glb_vel + base + 1),
                               __ldg(glb_vel + base + 2));
        v = qapply(inv, p);
    }

    // thread 0: rotated joint-0 position at t=0
    if (t == 0) {
        long base = ((long)b * T * J) * 3;
        float3 p = make_float3(__ldg(glb_pos + base),
                               __ldg(glb_pos + base + 1),
                               __ldg(glb_pos + base + 2));
        s_pos0 = qapply(inv, p);
    }

    // warp inclusive scan
    float3 s = v;
    #pragma unroll
    for (int o = 1; o < 32; o <<= 1) {
        float ax = __shfl_up_sync(0xFFFFFFFFu, s.x, o);
        float ay = __shfl_up_sync(0xFFFFFFFFu, s.y, o);
        float az = __shfl_up_sync(0xFFFFFFFFu, s.z, o);
        if (lane >= o) { s.x += ax; s.y += ay; s.z += az; }
    }
    if (lane == 31) s_wsum[warp] = s;
    __syncthreads();

    // warp 0 scans the 32 warp sums
    if (warp == 0) {
        float3 ws = s_wsum[lane];
        #pragma unroll
        for (int o = 1; o < 32; o <<= 1) {
            float ax = __shfl_up_sync(0xFFFFFFFFu, ws.x, o);
            float ay = __shfl_up_sync(0xFFFFFFFFu, ws.y, o);
            float az = __shfl_up_sync(0xFFFFFFFFu, ws.z, o);
            if (lane >= o) { ws.x += ax; ws.y += ay; ws.z += az; }
        }
        s_wsum[lane] = ws;   // inclusive scan of warp sums
    }
    __syncthreads();

    float3 prefix = (warp > 0) ? s_wsum[warp - 1] : make_float3(0.f, 0.f, 0.f);
    float3 incl = make_float3(s.x + prefix.x, s.y + prefix.y, s.z + prefix.z);

    // exact exclusive scan: shift inclusive down one lane
    float3 excl;
    excl.x = __shfl_up_sync(0xFFFFFFFFu, incl.x, 1);
    excl.y = __shfl_up_sync(0xFFFFFFFFu, incl.y, 1);
    excl.z = __shfl_up_sync(0xFFFFFFFFu, incl.z, 1);
    if (lane == 0) excl = prefix;

    float3 p0 = s_pos0;
    float3 out;
    out.x = p0.x + excl.x;
    out.y = 0.f;                 // xz mask pre-applied
    out.z = p0.z + excl.z;
    g_traj[b * T + t] = out;
}

// ---------------------------------------------------------------------------
// Kernel 2: elementwise. One thread per (b,t,j).
// pos_out = qapply(inv, pos) + traj[b,t]  (traj.y == 0)
// rot_out = standardize(qmul(inv, rot))
// ---------------------------------------------------------------------------
__global__ void __launch_bounds__(256) main_kernel(
    const float* __restrict__ glb_pos,
    const float4* __restrict__ glb_rot,
    const float4* __restrict__ root,
    float* __restrict__ out_pos,
    float4* __restrict__ out_rot,
    int T, int J, int total)
{
    int idx = blockIdx.x * blockDim.x + threadIdx.x;
    if (idx >= total) return;

    int tj = T * J;
    int b = idx / tj;
    int rem = idx - b * tj;
    int t = rem / J;

    Q inv = load_inv(root, b * T + t);

    // --- position path ---
    long pbase = (long)idx * 3;
    float3 p = make_float3(__ldg(glb_pos + pbase),
                           __ldg(glb_pos + pbase + 1),
                           __ldg(glb_pos + pbase + 2));
    float3 pr = qapply(inv, p);
    float3 tr = g_traj[b * T + t];
    out_pos[pbase]     = pr.x + tr.x;
    out_pos[pbase + 1] = pr.y;            // mask: y channel gets no trajectory
    out_pos[pbase + 2] = pr.z + tr.z;

    // --- rotation path ---
    float4 r4 = __ldg(glb_rot + idx);
    Q r; r.w = r4.x; r.x = r4.y; r.y = r4.z; r.z = r4.w;
    Q m = qmul(inv, r);
    if (m.w < 0.f) { m.w = -m.w; m.x = -m.x; m.y = -m.y; m.z = -m.z; }
    out_rot[idx] = make_float4(m.w, m.x, m.y, m.z);
}

extern "C" void kernel_launch(void* const* d_in, const int* in_sizes, int n_in,
                              void* d_out, int out_size)
{
    const float* glb_pos = (const float*)d_in[0];   // B*T*J*3
    const float* glb_rot = (const float*)d_in[1];   // B*T*J*4
    const float* glb_vel = (const float*)d_in[2];   // B*(T-1)*J*3
    const float* root    = (const float*)d_in[3];   // B*T*4

    // Derive dims: J = 4*pos/(3*root); B = (pos - vel)/(3J); T = root/(4B)
    int J = (int)((4LL * in_sizes[0]) / (3LL * in_sizes[3]));
    int B = (in_sizes[0] - in_sizes[2]) / (3 * J);
    int T = in_sizes[3] / (4 * B);

    int total = B * T * J;

    float*  out_pos = (float*)d_out;
    float4* out_rot = (float4*)((float*)d_out + (long)total * 3);

    traj_kernel<<<B, T>>>(glb_pos, glb_vel, (const float4*)root, T, J);

    int threads = 256;
    int blocks = (total + threads - 1) / threads;
    main_kernel<<<blocks, threads>>>(glb_pos, (const float4*)glb_rot,
                                     (const float4*)root,
                                     out_pos, out_rot, T, J, total);
}